// round 1
// baseline (speedup 1.0000x reference)
#include <cuda_runtime.h>
#include <cstddef>

#define N_NODES 8192
#define D_OSC   64
#define E_EDGES 1048576

// Scratch (device globals — no allocation allowed)
__device__ float d_P[N_NODES * D_OSC];      // normalized state_K
__device__ float d_g[N_NODES];              // tanh(state_H)
__device__ float d_fKacc[N_NODES * D_OSC];  // raw f_K accumulator

// -------------------------------------------------------------------------
// prep: normalize state_K rows -> d_P (warp per row), g = tanh(state_H),
//       fH = bias - state_H, zero d_fKacc.
// grid 1024 x 256  (8192 warps)
// -------------------------------------------------------------------------
__global__ void prep_kernel(const float* __restrict__ state_H,
                            const float* __restrict__ state_K,
                            const float* __restrict__ bias_H,
                            float* __restrict__ fH) {
    int tid  = blockIdx.x * blockDim.x + threadIdx.x;
    int warp = tid >> 5;
    int lane = threadIdx.x & 31;

    if (warp < N_NODES) {
        const float2* src = reinterpret_cast<const float2*>(state_K + warp * D_OSC);
        float2 u = src[lane];
        float ss = u.x * u.x + u.y * u.y;
        #pragma unroll
        for (int o = 16; o; o >>= 1) ss += __shfl_xor_sync(0xffffffffu, ss, o);
        float inv = rsqrtf(ss);
        float2* dst = reinterpret_cast<float2*>(d_P + warp * D_OSC);
        dst[lane] = make_float2(u.x * inv, u.y * inv);
    }
    if (tid < N_NODES) {
        float h = state_H[tid];
        d_g[tid] = tanhf(h);
        fH[tid]  = bias_H[tid] - h;
    }
    const int total = 1024 * 256;
    for (int i = tid; i < N_NODES * D_OSC; i += total) d_fKacc[i] = 0.0f;
}

__device__ __forceinline__ void red_add_v2(float* p, float a, float b) {
    asm volatile("red.global.add.v2.f32 [%0], {%1, %2};"
                 :: "l"(p), "f"(a), "f"(b) : "memory");
}

// -------------------------------------------------------------------------
// K edges: warp per edge. s = <P[j0],P[j1]>, coef = w_K*s;
//          fKacc[j0] += coef*P[j1], fKacc[j1] += coef*P[j0]
// -------------------------------------------------------------------------
__global__ void edgesK_kernel(const int* __restrict__ ind,
                              const float* __restrict__ wK) {
    int warp = (blockIdx.x * blockDim.x + threadIdx.x) >> 5;
    int lane = threadIdx.x & 31;
    if (warp >= E_EDGES) return;

    int i0 = __ldg(ind + 2 * warp);
    int i1 = __ldg(ind + 2 * warp + 1);

    float2 u = reinterpret_cast<const float2*>(d_P + i0 * D_OSC)[lane];
    float2 v = reinterpret_cast<const float2*>(d_P + i1 * D_OSC)[lane];
    float s = u.x * v.x + u.y * v.y;
    #pragma unroll
    for (int o = 16; o; o >>= 1) s += __shfl_xor_sync(0xffffffffu, s, o);

    float coef = __ldg(wK + warp) * s;
    red_add_v2(d_fKacc + i0 * D_OSC + 2 * lane, coef * v.x, coef * v.y);
    red_add_v2(d_fKacc + i1 * D_OSC + 2 * lane, coef * u.x, coef * u.y);
}

// -------------------------------------------------------------------------
// HK edges: warp per edge. Gram = <P[i0],P[i1]>;
//   fH[i0] += Gram*w*g[i1]/kH ; fH[i1] += Gram*w*g[i0]/kH
//   fKacc[i0] += -g0*g1*w/kK * P[i1] ; symmetric
// -------------------------------------------------------------------------
__global__ void edgesHK_kernel(const int* __restrict__ ind,
                               const float* __restrict__ wHK,
                               const float* __restrict__ kappaK,
                               const float* __restrict__ kappaH,
                               float* __restrict__ fH) {
    int warp = (blockIdx.x * blockDim.x + threadIdx.x) >> 5;
    int lane = threadIdx.x & 31;
    if (warp >= E_EDGES) return;

    int i0 = __ldg(ind + 2 * warp);
    int i1 = __ldg(ind + 2 * warp + 1);

    float2 u = reinterpret_cast<const float2*>(d_P + i0 * D_OSC)[lane];
    float2 v = reinterpret_cast<const float2*>(d_P + i1 * D_OSC)[lane];
    float s = u.x * v.x + u.y * v.y;
    #pragma unroll
    for (int o = 16; o; o >>= 1) s += __shfl_xor_sync(0xffffffffu, s, o);

    float w  = __ldg(wHK + warp);
    float g0 = d_g[i0];
    float g1 = d_g[i1];
    float invKH = 1.0f / kappaH[0];
    float invKK = 1.0f / kappaK[0];

    if (lane == 0) {
        atomicAdd(fH + i0, s * w * g1 * invKH);
        atomicAdd(fH + i1, s * w * g0 * invKH);
    }
    float G = -g0 * g1 * w * invKK;
    red_add_v2(d_fKacc + i0 * D_OSC + 2 * lane, G * v.x, G * v.y);
    red_add_v2(d_fKacc + i1 * D_OSC + 2 * lane, G * u.x, G * u.y);
}

// -------------------------------------------------------------------------
// y = W @ g : warp per row, coalesced float4, fH[r] += 0.5*y[r]
// -------------------------------------------------------------------------
__global__ void mvY_kernel(const float* __restrict__ W, float* __restrict__ fH) {
    int warp = (blockIdx.x * blockDim.x + threadIdx.x) >> 5;
    int lane = threadIdx.x & 31;
    if (warp >= N_NODES) return;

    const float4* row = reinterpret_cast<const float4*>(W + (size_t)warp * N_NODES);
    const float4* g4  = reinterpret_cast<const float4*>(d_g);
    float acc = 0.0f;
    #pragma unroll 8
    for (int c = lane; c < N_NODES / 4; c += 32) {
        float4 w4 = __ldg(row + c);
        float4 gg = g4[c];
        acc += w4.x * gg.x + w4.y * gg.y + w4.z * gg.z + w4.w * gg.w;
    }
    #pragma unroll
    for (int o = 16; o; o >>= 1) acc += __shfl_xor_sync(0xffffffffu, acc, o);
    if (lane == 0) atomicAdd(fH + warp, 0.5f * acc);
}

// -------------------------------------------------------------------------
// z = W^T @ g : thread per column, 16 row-chunks, fH[c] += 0.5*partial
// grid (32, 16) x 256
// -------------------------------------------------------------------------
__global__ void mvZ_kernel(const float* __restrict__ W, float* __restrict__ fH) {
    int c  = blockIdx.x * blockDim.x + threadIdx.x;       // column 0..8191
    int r0 = blockIdx.y * (N_NODES / 16);                 // 512-row chunk
    float a0 = 0.f, a1 = 0.f, a2 = 0.f, a3 = 0.f;
    const float* Wc = W + (size_t)r0 * N_NODES + c;
    #pragma unroll 4
    for (int r = 0; r < N_NODES / 16; r += 4) {
        a0 += __ldg(Wc + (size_t)(r + 0) * N_NODES) * d_g[r0 + r + 0];
        a1 += __ldg(Wc + (size_t)(r + 1) * N_NODES) * d_g[r0 + r + 1];
        a2 += __ldg(Wc + (size_t)(r + 2) * N_NODES) * d_g[r0 + r + 2];
        a3 += __ldg(Wc + (size_t)(r + 3) * N_NODES) * d_g[r0 + r + 3];
    }
    atomicAdd(fH + c, 0.5f * (a0 + a1 + a2 + a3));
}

// -------------------------------------------------------------------------
// finalize: f_K = -a + P * <P, a>  (warp per row)
// -------------------------------------------------------------------------
__global__ void finalize_kernel(float* __restrict__ fK) {
    int warp = (blockIdx.x * blockDim.x + threadIdx.x) >> 5;
    int lane = threadIdx.x & 31;
    if (warp >= N_NODES) return;

    float2 p = reinterpret_cast<const float2*>(d_P + warp * D_OSC)[lane];
    float2 a = reinterpret_cast<const float2*>(d_fKacc + warp * D_OSC)[lane];
    float dot = p.x * a.x + p.y * a.y;
    #pragma unroll
    for (int o = 16; o; o >>= 1) dot += __shfl_xor_sync(0xffffffffu, dot, o);

    float2 out = make_float2(-a.x + p.x * dot, -a.y + p.y * dot);
    reinterpret_cast<float2*>(fK + warp * D_OSC)[lane] = out;
}

// -------------------------------------------------------------------------
extern "C" void kernel_launch(void* const* d_in, const int* in_sizes, int n_in,
                              void* d_out, int out_size) {
    const float* state_H    = (const float*)d_in[0];
    const float* state_K    = (const float*)d_in[1];
    const int*   ind_K      = (const int*)  d_in[2];
    const int*   ind_HK     = (const int*)  d_in[3];
    const float* kappa_K    = (const float*)d_in[4];
    const float* kappa_H    = (const float*)d_in[5];
    const float* weights_H  = (const float*)d_in[6];
    const float* bias_H     = (const float*)d_in[7];
    const float* weights_HK = (const float*)d_in[8];
    const float* w_K        = (const float*)d_in[9];

    float* fH = (float*)d_out;            // [8192]
    float* fK = fH + N_NODES;             // [8192 * 64]

    prep_kernel<<<1024, 256>>>(state_H, state_K, bias_H, fH);
    edgesK_kernel<<<E_EDGES / 8, 256>>>(ind_K, w_K);
    edgesHK_kernel<<<E_EDGES / 8, 256>>>(ind_HK, weights_HK, kappa_K, kappa_H, fH);
    mvY_kernel<<<N_NODES / 8, 256>>>(weights_H, fH);
    {
        dim3 gz(N_NODES / 256, 16);
        mvZ_kernel<<<gz, 256>>>(weights_H, fH);
    }
    finalize_kernel<<<N_NODES / 8, 256>>>(fK);
}

// round 2
// speedup vs baseline: 1.2056x; 1.2056x over previous
#include <cuda_runtime.h>
#include <cstddef>

#define N_NODES 8192
#define D_OSC   64
#define E_EDGES 1048576

// MV tiling: 64-row strips x 4096-col halves -> 256 MV blocks
#define R_TILE    64
#define MV_BLOCKS 256
// Edge blocks: 8 warps x 2 edges = 16 edges/block
#define EK_BLOCKS  (E_EDGES / 16)   // 65536
#define EHK_BLOCKS (E_EDGES / 16)   // 65536

// Scratch (device globals — no allocation allowed)
__device__ float d_P[N_NODES * D_OSC];      // normalized state_K
__device__ float d_g[N_NODES];              // tanh(state_H)
__device__ float d_fKacc[N_NODES * D_OSC];  // raw f_K accumulator

// -------------------------------------------------------------------------
// prep: normalize state_K rows -> d_P (warp per row), g = tanh(state_H),
//       fH = bias - state_H, zero d_fKacc.
// -------------------------------------------------------------------------
__global__ void prep_kernel(const float* __restrict__ state_H,
                            const float* __restrict__ state_K,
                            const float* __restrict__ bias_H,
                            float* __restrict__ fH) {
    int tid  = blockIdx.x * blockDim.x + threadIdx.x;
    int warp = tid >> 5;
    int lane = threadIdx.x & 31;

    if (warp < N_NODES) {
        const float2* src = reinterpret_cast<const float2*>(state_K + warp * D_OSC);
        float2 u = src[lane];
        float ss = u.x * u.x + u.y * u.y;
        #pragma unroll
        for (int o = 16; o; o >>= 1) ss += __shfl_xor_sync(0xffffffffu, ss, o);
        float inv = rsqrtf(ss);
        float2* dst = reinterpret_cast<float2*>(d_P + warp * D_OSC);
        dst[lane] = make_float2(u.x * inv, u.y * inv);
    }
    if (tid < N_NODES) {
        float h = state_H[tid];
        d_g[tid] = tanhf(h);
        fH[tid]  = bias_H[tid] - h;
    }
    const int total = 1024 * 256;
    for (int i = tid; i < N_NODES * D_OSC; i += total) d_fKacc[i] = 0.0f;
}

__device__ __forceinline__ void red_add_v4(float* p, float a, float b, float c, float d) {
    asm volatile("red.global.add.v4.f32 [%0], {%1, %2, %3, %4};"
                 :: "l"(p), "f"(a), "f"(b), "f"(c), "f"(d) : "memory");
}

// -------------------------------------------------------------------------
// Edge work: 2 edges per warp (half-warp per edge), float4 gathers + v4 red.
// -------------------------------------------------------------------------
__device__ __forceinline__ void edge_work(const int* __restrict__ ind,
                                          const float* __restrict__ wvec,
                                          int eblk, bool isHK,
                                          float invKK, float invKH,
                                          float* __restrict__ fH) {
    int warp = threadIdx.x >> 5;
    int lane = threadIdx.x & 31;
    int half = lane >> 4;        // which edge in this warp
    int hl   = lane & 15;        // lane within half-warp

    int e  = eblk * 16 + warp * 2 + half;
    int i0 = __ldg(ind + 2 * e);
    int i1 = __ldg(ind + 2 * e + 1);

    const float4* P0 = reinterpret_cast<const float4*>(d_P + i0 * D_OSC);
    const float4* P1 = reinterpret_cast<const float4*>(d_P + i1 * D_OSC);
    float4 u = __ldg(P0 + hl);
    float4 v = __ldg(P1 + hl);

    float s = u.x * v.x + u.y * v.y + u.z * v.z + u.w * v.w;
    #pragma unroll
    for (int o = 8; o; o >>= 1) s += __shfl_xor_sync(0xffffffffu, s, o);

    float w = __ldg(wvec + e);
    float cu, cv;                // coefficients for scatter into fKacc
    if (!isHK) {
        float coef = w * s;      // dE_ds
        cu = coef; cv = coef;
    } else {
        float g0 = __ldg(d_g + i0);
        float g1 = __ldg(d_g + i1);
        if (hl == 0) {
            float t = s * w * invKH;
            atomicAdd(fH + i0, t * g1);
            atomicAdd(fH + i1, t * g0);
        }
        float G = -g0 * g1 * w * invKK;
        cu = G; cv = G;
    }
    float* r0 = d_fKacc + i0 * D_OSC + hl * 4;
    float* r1 = d_fKacc + i1 * D_OSC + hl * 4;
    red_add_v4(r0, cv * v.x, cv * v.y, cv * v.z, cv * v.w);
    red_add_v4(r1, cu * u.x, cu * u.y, cu * u.z, cu * u.w);
}

// -------------------------------------------------------------------------
// Fused matvec tile: one pass over W computes both W@g (y) and W^T@g (z).
// Block = 8 warps; warp covers 512 consecutive cols; tile = 64 rows x 4096 cols.
// z accumulated in registers per lane (16 cols), y warp-reduced per row.
// -------------------------------------------------------------------------
__device__ __forceinline__ void mv_work(const float* __restrict__ W,
                                        float* __restrict__ fH, int bid) {
    int strip = bid >> 1;            // 0..127 -> rows [strip*64, +64)
    int chalf = bid & 1;             // 0..1   -> cols [chalf*4096, +4096)
    int warp  = threadIdx.x >> 5;
    int lane  = threadIdx.x & 31;

    int r0    = strip * R_TILE;
    int cbase = chalf * 4096 + warp * 512;   // warp's 512-col span

    // per-lane columns: cbase + k*128 + lane*4 + {0..3},  k = 0..3
    float4 gv[4];
    float4 za[4];
    #pragma unroll
    for (int k = 0; k < 4; k++) {
        gv[k] = *reinterpret_cast<const float4*>(d_g + cbase + k * 128 + lane * 4);
        za[k] = make_float4(0.f, 0.f, 0.f, 0.f);
    }

    for (int r = 0; r < R_TILE; r++) {
        float gr = d_g[r0 + r];
        const float4* Wrow = reinterpret_cast<const float4*>(
            W + (size_t)(r0 + r) * N_NODES + cbase);
        float yp = 0.0f;
        #pragma unroll
        for (int k = 0; k < 4; k++) {
            float4 w4 = __ldg(Wrow + k * 32 + lane);
            yp += w4.x * gv[k].x + w4.y * gv[k].y + w4.z * gv[k].z + w4.w * gv[k].w;
            za[k].x += w4.x * gr;
            za[k].y += w4.y * gr;
            za[k].z += w4.z * gr;
            za[k].w += w4.w * gr;
        }
        #pragma unroll
        for (int o = 16; o; o >>= 1) yp += __shfl_xor_sync(0xffffffffu, yp, o);
        if (lane == 0) atomicAdd(fH + r0 + r, 0.5f * yp);
    }
    #pragma unroll
    for (int k = 0; k < 4; k++) {
        int c = cbase + k * 128 + lane * 4;
        atomicAdd(fH + c + 0, 0.5f * za[k].x);
        atomicAdd(fH + c + 1, 0.5f * za[k].y);
        atomicAdd(fH + c + 2, 0.5f * za[k].z);
        atomicAdd(fH + c + 3, 0.5f * za[k].w);
    }
}

// -------------------------------------------------------------------------
// Mega-kernel: blockIdx partitions work.
//   [0, 256)                      : fused matvec tiles (DRAM-bound, start first)
//   [256, 256 + 2*65536)          : edge blocks, interleaved K/HK
// -------------------------------------------------------------------------
__global__ void __launch_bounds__(256)
mega_kernel(const float* __restrict__ W,
            const int*   __restrict__ ind_K,
            const float* __restrict__ w_K,
            const int*   __restrict__ ind_HK,
            const float* __restrict__ w_HK,
            const float* __restrict__ kappa_K,
            const float* __restrict__ kappa_H,
            float* __restrict__ fH) {
    int bid = blockIdx.x;
    if (bid < MV_BLOCKS) {
        mv_work(W, fH, bid);
    } else {
        int e = bid - MV_BLOCKS;
        int eblk = e >> 1;
        if (e & 1) {
            float invKK = 1.0f / __ldg(kappa_K);
            float invKH = 1.0f / __ldg(kappa_H);
            edge_work(ind_HK, w_HK, eblk, true, invKK, invKH, fH);
        } else {
            edge_work(ind_K, w_K, eblk, false, 0.f, 0.f, fH);
        }
    }
}

// -------------------------------------------------------------------------
// finalize: f_K = -a + P * <P, a>  (warp per row, float4)
// -------------------------------------------------------------------------
__global__ void finalize_kernel(float* __restrict__ fK) {
    int warp = (blockIdx.x * blockDim.x + threadIdx.x) >> 5;
    int lane = threadIdx.x & 31;
    int half = lane >> 4;
    int hl   = lane & 15;
    // two rows per warp
    int row = warp * 2 + half;
    if (row >= N_NODES) return;

    float4 p = *reinterpret_cast<const float4*>(d_P + row * D_OSC + hl * 4);
    float4 a = *reinterpret_cast<const float4*>(d_fKacc + row * D_OSC + hl * 4);
    float dot = p.x * a.x + p.y * a.y + p.z * a.z + p.w * a.w;
    #pragma unroll
    for (int o = 8; o; o >>= 1) dot += __shfl_xor_sync(0xffffffffu, dot, o);

    float4 out = make_float4(-a.x + p.x * dot, -a.y + p.y * dot,
                             -a.z + p.z * dot, -a.w + p.w * dot);
    *reinterpret_cast<float4*>(fK + row * D_OSC + hl * 4) = out;
}

// -------------------------------------------------------------------------
extern "C" void kernel_launch(void* const* d_in, const int* in_sizes, int n_in,
                              void* d_out, int out_size) {
    const float* state_H    = (const float*)d_in[0];
    const float* state_K    = (const float*)d_in[1];
    const int*   ind_K      = (const int*)  d_in[2];
    const int*   ind_HK     = (const int*)  d_in[3];
    const float* kappa_K    = (const float*)d_in[4];
    const float* kappa_H    = (const float*)d_in[5];
    const float* weights_H  = (const float*)d_in[6];
    const float* bias_H     = (const float*)d_in[7];
    const float* weights_HK = (const float*)d_in[8];
    const float* w_K        = (const float*)d_in[9];

    float* fH = (float*)d_out;            // [8192]
    float* fK = fH + N_NODES;             // [8192 * 64]

    prep_kernel<<<1024, 256>>>(state_H, state_K, bias_H, fH);
    mega_kernel<<<MV_BLOCKS + EK_BLOCKS + EHK_BLOCKS, 256>>>(
        weights_H, ind_K, w_K, ind_HK, weights_HK, kappa_K, kappa_H, fH);
    finalize_kernel<<<N_NODES / 16, 256>>>(fK);
}

// round 4
// speedup vs baseline: 1.3059x; 1.0832x over previous
#include <cuda_runtime.h>
#include <cstddef>

#define N_NODES 8192
#define D_OSC   64
#define E_EDGES 1048576
#define CAP     512          // slots per node per list (Binomial mean 256, sd 16)

// MV tiling: 64-row strips x 4096-col halves -> 256 MV blocks
#define R_TILE    64
#define MV_BLOCKS 256
#define NODE_BLOCKS (N_NODES / 8)   // 8 warps/block, warp per node

// Scratch (device globals — no allocation allowed)
__device__ float d_P[N_NODES * D_OSC];      // normalized state_K
__device__ float d_g[N_NODES];              // tanh(state_H)
__device__ int   d_cntK[N_NODES];
__device__ int   d_cntHK[N_NODES];
__device__ int2  d_slotK[N_NODES * CAP];    // (other, w) per endpoint, 32MB
__device__ int2  d_slotHK[N_NODES * CAP];   // 32MB

// -------------------------------------------------------------------------
// prep: normalize state_K rows -> d_P, g = tanh(state_H),
//       fH = bias - state_H, zero slot counters.
// -------------------------------------------------------------------------
__global__ void prep_kernel(const float* __restrict__ state_H,
                            const float* __restrict__ state_K,
                            const float* __restrict__ bias_H,
                            float* __restrict__ fH) {
    int tid  = blockIdx.x * blockDim.x + threadIdx.x;
    int warp = tid >> 5;
    int lane = threadIdx.x & 31;

    if (warp < N_NODES) {
        const float2* src = reinterpret_cast<const float2*>(state_K + warp * D_OSC);
        float2 u = src[lane];
        float ss = u.x * u.x + u.y * u.y;
        #pragma unroll
        for (int o = 16; o; o >>= 1) ss += __shfl_xor_sync(0xffffffffu, ss, o);
        float inv = rsqrtf(ss);
        float2* dst = reinterpret_cast<float2*>(d_P + warp * D_OSC);
        dst[lane] = make_float2(u.x * inv, u.y * inv);
    }
    if (tid < N_NODES) {
        float h = state_H[tid];
        d_g[tid] = tanhf(h);
        fH[tid]  = bias_H[tid] - h;
        d_cntK[tid]  = 0;
        d_cntHK[tid] = 0;
    }
}

// -------------------------------------------------------------------------
// fill: build per-node endpoint lists for both edge arrays.
// thread per edge; threads [0,E) -> K edges, [E,2E) -> HK edges.
// -------------------------------------------------------------------------
__global__ void fill_kernel(const int*   __restrict__ indK,
                            const float* __restrict__ wK,
                            const int*   __restrict__ indHK,
                            const float* __restrict__ wHK) {
    int e = blockIdx.x * blockDim.x + threadIdx.x;
    if (e < E_EDGES) {
        int i0 = __ldg(indK + 2 * e);
        int i1 = __ldg(indK + 2 * e + 1);
        int wi = __float_as_int(__ldg(wK + e));
        int p0 = atomicAdd(d_cntK + i0, 1);
        if (p0 < CAP) d_slotK[i0 * CAP + p0] = make_int2(i1, wi);
        int p1 = atomicAdd(d_cntK + i1, 1);
        if (p1 < CAP) d_slotK[i1 * CAP + p1] = make_int2(i0, wi);
    } else {
        e -= E_EDGES;
        int i0 = __ldg(indHK + 2 * e);
        int i1 = __ldg(indHK + 2 * e + 1);
        int wi = __float_as_int(__ldg(wHK + e));
        int p0 = atomicAdd(d_cntHK + i0, 1);
        if (p0 < CAP) d_slotHK[i0 * CAP + p0] = make_int2(i1, wi);
        int p1 = atomicAdd(d_cntHK + i1, 1);
        if (p1 < CAP) d_slotHK[i1 * CAP + p1] = make_int2(i0, wi);
    }
}

// -------------------------------------------------------------------------
// Node gather: warp per node. Lower half-warp walks the K list, upper
// half-warp walks the HK list. Each half-lane owns 4 osc dims (float4).
// Accumulate f_K contribution a in registers, then emit
//   f_K[n] = -a + P[n] * <P[n], a>   and   fH[n] += (HK sum)/kappa_H.
// -------------------------------------------------------------------------
__device__ __forceinline__ void node_work(float* __restrict__ fH,
                                          float* __restrict__ fK,
                                          int node, float invKK, float invKH) {
    int lane = threadIdx.x & 31;
    int isHK = lane >> 4;
    int hl   = lane & 15;
    unsigned hmask = isHK ? 0xffff0000u : 0x0000ffffu;

    float4 p = *reinterpret_cast<const float4*>(d_P + node * D_OSC + hl * 4);
    float  gn = __ldg(d_g + node);

    int cnt = isHK ? __ldg(d_cntHK + node) : __ldg(d_cntK + node);
    if (cnt > CAP) cnt = CAP;
    const int2* slots = (isHK ? d_slotHK : d_slotK) + node * CAP;

    float4 acc = make_float4(0.f, 0.f, 0.f, 0.f);
    float  fhsum = 0.0f;     // NOTE: after the loop, identical across the 16
                             // HK lanes (s is warp-reduced) — no reduction!

    for (int k = 0; k < cnt; k++) {
        int2 ent = __ldg(slots + k);
        int other = ent.x;
        float w   = __int_as_float(ent.y);
        float4 v  = __ldg(reinterpret_cast<const float4*>(d_P + other * D_OSC) + hl);

        float s = v.x * p.x + v.y * p.y + v.z * p.z + v.w * p.w;
        #pragma unroll
        for (int o = 8; o; o >>= 1) s += __shfl_xor_sync(hmask, s, o);

        float coef;
        if (isHK) {
            float go = __ldg(d_g + other);
            fhsum += s * w * go;
            coef = -gn * go * w;      // invKK folded in after the loop
        } else {
            coef = w * s;
        }
        acc.x += coef * v.x;
        acc.y += coef * v.y;
        acc.z += coef * v.z;
        acc.w += coef * v.w;
    }
    if (isHK) {
        acc.x *= invKK; acc.y *= invKK; acc.z *= invKK; acc.w *= invKK;
    }
    __syncwarp();

    // fH contribution: all 16 HK lanes hold the same fhsum -> exactly one add
    if (lane == 16) atomicAdd(fH + node, fhsum * invKH);

    // combine halves: both halves end with acc = accK + accHK (same dims)
    acc.x += __shfl_xor_sync(0xffffffffu, acc.x, 16);
    acc.y += __shfl_xor_sync(0xffffffffu, acc.y, 16);
    acc.z += __shfl_xor_sync(0xffffffffu, acc.z, 16);
    acc.w += __shfl_xor_sync(0xffffffffu, acc.w, 16);

    // projection: dot over the 16-lane half (values duplicated across halves)
    float dot = p.x * acc.x + p.y * acc.y + p.z * acc.z + p.w * acc.w;
    #pragma unroll
    for (int o = 8; o; o >>= 1) dot += __shfl_xor_sync(0xffffffffu, dot, o);

    if (!isHK) {
        float4 out = make_float4(-acc.x + p.x * dot, -acc.y + p.y * dot,
                                 -acc.z + p.z * dot, -acc.w + p.w * dot);
        *reinterpret_cast<float4*>(fK + node * D_OSC + hl * 4) = out;
    }
}

// -------------------------------------------------------------------------
// Fused matvec tile: one pass over W computes both W@g (y) and W^T@g (z).
// -------------------------------------------------------------------------
__device__ __forceinline__ void mv_work(const float* __restrict__ W,
                                        float* __restrict__ fH, int bid) {
    int strip = bid >> 1;
    int chalf = bid & 1;
    int warp  = threadIdx.x >> 5;
    int lane  = threadIdx.x & 31;

    int r0    = strip * R_TILE;
    int cbase = chalf * 4096 + warp * 512;

    float4 gv[4];
    float4 za[4];
    #pragma unroll
    for (int k = 0; k < 4; k++) {
        gv[k] = *reinterpret_cast<const float4*>(d_g + cbase + k * 128 + lane * 4);
        za[k] = make_float4(0.f, 0.f, 0.f, 0.f);
    }

    for (int r = 0; r < R_TILE; r++) {
        float gr = d_g[r0 + r];
        const float4* Wrow = reinterpret_cast<const float4*>(
            W + (size_t)(r0 + r) * N_NODES + cbase);
        float yp = 0.0f;
        #pragma unroll
        for (int k = 0; k < 4; k++) {
            float4 w4 = __ldg(Wrow + k * 32 + lane);
            yp += w4.x * gv[k].x + w4.y * gv[k].y + w4.z * gv[k].z + w4.w * gv[k].w;
            za[k].x += w4.x * gr;
            za[k].y += w4.y * gr;
            za[k].z += w4.z * gr;
            za[k].w += w4.w * gr;
        }
        #pragma unroll
        for (int o = 16; o; o >>= 1) yp += __shfl_xor_sync(0xffffffffu, yp, o);
        if (lane == 0) atomicAdd(fH + r0 + r, 0.5f * yp);
    }
    #pragma unroll
    for (int k = 0; k < 4; k++) {
        int c = cbase + k * 128 + lane * 4;
        atomicAdd(fH + c + 0, 0.5f * za[k].x);
        atomicAdd(fH + c + 1, 0.5f * za[k].y);
        atomicAdd(fH + c + 2, 0.5f * za[k].z);
        atomicAdd(fH + c + 3, 0.5f * za[k].w);
    }
}

// -------------------------------------------------------------------------
// Mega-kernel: blockIdx partitions work.
//   [0, MV_BLOCKS)       : fused matvec tiles (DRAM-bound)
//   [MV_BLOCKS, +1024)   : node-gather blocks (L2-bound), 8 nodes/block
// -------------------------------------------------------------------------
__global__ void __launch_bounds__(256)
mega_kernel(const float* __restrict__ W,
            const float* __restrict__ kappa_K,
            const float* __restrict__ kappa_H,
            float* __restrict__ fH,
            float* __restrict__ fK) {
    int bid = blockIdx.x;
    if (bid < MV_BLOCKS) {
        mv_work(W, fH, bid);
    } else {
        int node = (bid - MV_BLOCKS) * 8 + (threadIdx.x >> 5);
        float invKK = 1.0f / __ldg(kappa_K);
        float invKH = 1.0f / __ldg(kappa_H);
        node_work(fH, fK, node, invKK, invKH);
    }
}

// -------------------------------------------------------------------------
extern "C" void kernel_launch(void* const* d_in, const int* in_sizes, int n_in,
                              void* d_out, int out_size) {
    const float* state_H    = (const float*)d_in[0];
    const float* state_K    = (const float*)d_in[1];
    const int*   ind_K      = (const int*)  d_in[2];
    const int*   ind_HK     = (const int*)  d_in[3];
    const float* kappa_K    = (const float*)d_in[4];
    const float* kappa_H    = (const float*)d_in[5];
    const float* weights_H  = (const float*)d_in[6];
    const float* bias_H     = (const float*)d_in[7];
    const float* weights_HK = (const float*)d_in[8];
    const float* w_K        = (const float*)d_in[9];

    float* fH = (float*)d_out;            // [8192]
    float* fK = fH + N_NODES;             // [8192 * 64]

    prep_kernel<<<1024, 256>>>(state_H, state_K, bias_H, fH);
    fill_kernel<<<(2 * E_EDGES) / 256, 256>>>(ind_K, w_K, ind_HK, weights_HK);
    mega_kernel<<<MV_BLOCKS + NODE_BLOCKS, 256>>>(
        weights_H, kappa_K, kappa_H, fH, fK);
}

// round 5
// speedup vs baseline: 1.4417x; 1.1040x over previous
#include <cuda_runtime.h>
#include <cstddef>

#define N_NODES 8192
#define D_OSC   64
#define E_EDGES 1048576
#define CAP     512          // slots per node per list (mean 256, sd 16)

#define R_TILE    64
#define MV_BLOCKS 256
#define FILL_BLOCKS ((2 * E_EDGES) / 256)   // 8192
#define NODE_BLOCKS (N_NODES / 8)           // 1024

#define QSCALE     32767.0f
#define QSCALE_INV (1.0f / 32767.0f)

// Scratch (device globals — no allocation allowed)
__device__ float d_P[N_NODES * D_OSC];      // normalized state_K (fp32, own-row reads)
__device__ short d_Pq[N_NODES * D_OSC];     // int16-quantized P (gather reads), 1MB
__device__ float d_g[N_NODES];              // tanh(state_H)
__device__ int   d_cntK[N_NODES];
__device__ int   d_cntHK[N_NODES];
__device__ int2  d_slotK[N_NODES * CAP];    // (other, w)
__device__ int2  d_slotHK[N_NODES * CAP];   // (other, w * g[other])

// -------------------------------------------------------------------------
// prep: normalize state_K rows -> d_P + d_Pq, g = tanh(state_H),
//       fH = bias - state_H, zero slot counters.
// -------------------------------------------------------------------------
__global__ void prep_kernel(const float* __restrict__ state_H,
                            const float* __restrict__ state_K,
                            const float* __restrict__ bias_H,
                            float* __restrict__ fH) {
    int tid  = blockIdx.x * blockDim.x + threadIdx.x;
    int warp = tid >> 5;
    int lane = threadIdx.x & 31;

    if (warp < N_NODES) {
        const float2* src = reinterpret_cast<const float2*>(state_K + warp * D_OSC);
        float2 u = src[lane];
        float ss = u.x * u.x + u.y * u.y;
        #pragma unroll
        for (int o = 16; o; o >>= 1) ss += __shfl_xor_sync(0xffffffffu, ss, o);
        float inv = rsqrtf(ss);
        float2 val = make_float2(u.x * inv, u.y * inv);
        reinterpret_cast<float2*>(d_P + warp * D_OSC)[lane] = val;
        short2 q;
        q.x = (short)__float2int_rn(val.x * QSCALE);
        q.y = (short)__float2int_rn(val.y * QSCALE);
        reinterpret_cast<short2*>(d_Pq + warp * D_OSC)[lane] = q;
    }
    if (tid < N_NODES) {
        float h = state_H[tid];
        d_g[tid] = tanhf(h);
        fH[tid]  = bias_H[tid] - h;
        d_cntK[tid]  = 0;
        d_cntHK[tid] = 0;
    }
}

// -------------------------------------------------------------------------
// Fused matvec tile: one pass over W computes both W@g (y) and W^T@g (z).
// -------------------------------------------------------------------------
__device__ __forceinline__ void mv_work(const float* __restrict__ W,
                                        float* __restrict__ fH, int bid) {
    int strip = bid >> 1;
    int chalf = bid & 1;
    int warp  = threadIdx.x >> 5;
    int lane  = threadIdx.x & 31;

    int r0    = strip * R_TILE;
    int cbase = chalf * 4096 + warp * 512;

    float4 gv[4];
    float4 za[4];
    #pragma unroll
    for (int k = 0; k < 4; k++) {
        gv[k] = *reinterpret_cast<const float4*>(d_g + cbase + k * 128 + lane * 4);
        za[k] = make_float4(0.f, 0.f, 0.f, 0.f);
    }

    for (int r = 0; r < R_TILE; r++) {
        float gr = d_g[r0 + r];
        const float4* Wrow = reinterpret_cast<const float4*>(
            W + (size_t)(r0 + r) * N_NODES + cbase);
        float yp = 0.0f;
        #pragma unroll
        for (int k = 0; k < 4; k++) {
            float4 w4 = __ldg(Wrow + k * 32 + lane);
            yp += w4.x * gv[k].x + w4.y * gv[k].y + w4.z * gv[k].z + w4.w * gv[k].w;
            za[k].x += w4.x * gr;
            za[k].y += w4.y * gr;
            za[k].z += w4.z * gr;
            za[k].w += w4.w * gr;
        }
        #pragma unroll
        for (int o = 16; o; o >>= 1) yp += __shfl_xor_sync(0xffffffffu, yp, o);
        if (lane == 0) atomicAdd(fH + r0 + r, 0.5f * yp);
    }
    #pragma unroll
    for (int k = 0; k < 4; k++) {
        int c = cbase + k * 128 + lane * 4;
        atomicAdd(fH + c + 0, 0.5f * za[k].x);
        atomicAdd(fH + c + 1, 0.5f * za[k].y);
        atomicAdd(fH + c + 2, 0.5f * za[k].z);
        atomicAdd(fH + c + 3, 0.5f * za[k].w);
    }
}

// -------------------------------------------------------------------------
// fillmv: blocks [0, MV_BLOCKS) do the fused matvec (DRAM-bound);
//         remaining blocks build per-node endpoint lists (latency-bound).
// HK slots store (other, w * g[other]) so the gather never reads g.
// -------------------------------------------------------------------------
__global__ void __launch_bounds__(256)
fillmv_kernel(const float* __restrict__ W,
              const int*   __restrict__ indK,
              const float* __restrict__ wK,
              const int*   __restrict__ indHK,
              const float* __restrict__ wHK,
              float* __restrict__ fH) {
    int bid = blockIdx.x;
    if (bid < MV_BLOCKS) {
        mv_work(W, fH, bid);
        return;
    }
    int e = (bid - MV_BLOCKS) * 256 + threadIdx.x;
    if (e < E_EDGES) {
        int i0 = __ldg(indK + 2 * e);
        int i1 = __ldg(indK + 2 * e + 1);
        int wi = __float_as_int(__ldg(wK + e));
        int p0 = atomicAdd(d_cntK + i0, 1);
        if (p0 < CAP) d_slotK[i0 * CAP + p0] = make_int2(i1, wi);
        int p1 = atomicAdd(d_cntK + i1, 1);
        if (p1 < CAP) d_slotK[i1 * CAP + p1] = make_int2(i0, wi);
    } else {
        e -= E_EDGES;
        int i0 = __ldg(indHK + 2 * e);
        int i1 = __ldg(indHK + 2 * e + 1);
        float w = __ldg(wHK + e);
        float wg1 = w * __ldg(d_g + i1);   // stored with endpoint i0
        float wg0 = w * __ldg(d_g + i0);   // stored with endpoint i1
        int p0 = atomicAdd(d_cntHK + i0, 1);
        if (p0 < CAP) d_slotHK[i0 * CAP + p0] = make_int2(i1, __float_as_int(wg1));
        int p1 = atomicAdd(d_cntHK + i1, 1);
        if (p1 < CAP) d_slotHK[i1 * CAP + p1] = make_int2(i0, __float_as_int(wg0));
    }
}

// -------------------------------------------------------------------------
// Gather: warp per node. Lower half-warp = K list, upper half-warp = HK list.
// Each half-lane owns 4 osc dims. v rows read int16-quantized (128B/row).
// Raw-int dots; scales folded once per node:
//   K contribution  = w * sraw * v_raw * SC^2
//   HK contribution = -(w*g_other) * g_n * v_raw * SC  (and fhsum raw * SC)
// -------------------------------------------------------------------------
__device__ __forceinline__ void decode4(int2 q, float& v0, float& v1,
                                        float& v2, float& v3) {
    v0 = (float)(short)(q.x);
    v1 = (float)(q.x >> 16);
    v2 = (float)(short)(q.y);
    v3 = (float)(q.y >> 16);
}

__global__ void __launch_bounds__(256)
gather_kernel(const float* __restrict__ kappa_K,
              const float* __restrict__ kappa_H,
              float* __restrict__ fH,
              float* __restrict__ fK) {
    int node = blockIdx.x * 8 + (threadIdx.x >> 5);
    int lane = threadIdx.x & 31;
    int isHK = lane >> 4;
    int hl   = lane & 15;
    unsigned hmask = isHK ? 0xffff0000u : 0x0000ffffu;

    float4 p = *reinterpret_cast<const float4*>(d_P + node * D_OSC + hl * 4);
    float  gn = __ldg(d_g + node);

    int cnt = isHK ? __ldg(d_cntHK + node) : __ldg(d_cntK + node);
    if (cnt > CAP) cnt = CAP;
    const int2* slots = (isHK ? d_slotHK : d_slotK) + node * CAP;

    float ax = 0.f, ay = 0.f, az = 0.f, aw = 0.f;
    float fhraw = 0.0f;   // identical across HK lanes after loop (s is reduced)

    int k = 0;
    for (; k + 2 <= cnt; k += 2) {
        int2 e0 = __ldg(slots + k);
        int2 e1 = __ldg(slots + k + 1);
        int2 q0 = __ldg(reinterpret_cast<const int2*>(d_Pq + e0.x * D_OSC) + hl);
        int2 q1 = __ldg(reinterpret_cast<const int2*>(d_Pq + e1.x * D_OSC) + hl);

        float u0, u1, u2, u3, t0, t1, t2, t3;
        decode4(q0, u0, u1, u2, u3);
        decode4(q1, t0, t1, t2, t3);

        float s0 = p.x * u0 + p.y * u1 + p.z * u2 + p.w * u3;
        float s1 = p.x * t0 + p.y * t1 + p.z * t2 + p.w * t3;
        #pragma unroll
        for (int o = 8; o; o >>= 1) {
            s0 += __shfl_xor_sync(hmask, s0, o);
            s1 += __shfl_xor_sync(hmask, s1, o);
        }
        float w0 = __int_as_float(e0.y);
        float w1 = __int_as_float(e1.y);
        float c0, c1;
        if (isHK) {
            fhraw += s0 * w0 + s1 * w1;   // w here is w*g_other
            c0 = -gn * w0;
            c1 = -gn * w1;
        } else {
            c0 = w0 * s0;
            c1 = w1 * s1;
        }
        ax += c0 * u0 + c1 * t0;
        ay += c0 * u1 + c1 * t1;
        az += c0 * u2 + c1 * t2;
        aw += c0 * u3 + c1 * t3;
    }
    if (k < cnt) {
        int2 e0 = __ldg(slots + k);
        int2 q0 = __ldg(reinterpret_cast<const int2*>(d_Pq + e0.x * D_OSC) + hl);
        float u0, u1, u2, u3;
        decode4(q0, u0, u1, u2, u3);
        float s0 = p.x * u0 + p.y * u1 + p.z * u2 + p.w * u3;
        #pragma unroll
        for (int o = 8; o; o >>= 1) s0 += __shfl_xor_sync(hmask, s0, o);
        float w0 = __int_as_float(e0.y);
        float c0;
        if (isHK) { fhraw += s0 * w0; c0 = -gn * w0; }
        else      { c0 = w0 * s0; }
        ax += c0 * u0; ay += c0 * u1; az += c0 * u2; aw += c0 * u3;
    }

    float invKK = 1.0f / __ldg(kappa_K);
    float invKH = 1.0f / __ldg(kappa_H);
    float sc = isHK ? (QSCALE_INV * invKK) : (QSCALE_INV * QSCALE_INV);
    ax *= sc; ay *= sc; az *= sc; aw *= sc;
    __syncwarp();

    // fH: every HK lane holds the same fhraw -> exactly one atomic
    if (lane == 16) atomicAdd(fH + node, fhraw * QSCALE_INV * invKH);

    // combine halves (acc = accK + accHK per dim)
    ax += __shfl_xor_sync(0xffffffffu, ax, 16);
    ay += __shfl_xor_sync(0xffffffffu, ay, 16);
    az += __shfl_xor_sync(0xffffffffu, az, 16);
    aw += __shfl_xor_sync(0xffffffffu, aw, 16);

    // projection f_K = -a + P * <P, a>
    float dot = p.x * ax + p.y * ay + p.z * az + p.w * aw;
    #pragma unroll
    for (int o = 8; o; o >>= 1) dot += __shfl_xor_sync(0xffffffffu, dot, o);

    if (!isHK) {
        float4 out = make_float4(-ax + p.x * dot, -ay + p.y * dot,
                                 -az + p.z * dot, -aw + p.w * dot);
        *reinterpret_cast<float4*>(fK + node * D_OSC + hl * 4) = out;
    }
}

// -------------------------------------------------------------------------
extern "C" void kernel_launch(void* const* d_in, const int* in_sizes, int n_in,
                              void* d_out, int out_size) {
    const float* state_H    = (const float*)d_in[0];
    const float* state_K    = (const float*)d_in[1];
    const int*   ind_K      = (const int*)  d_in[2];
    const int*   ind_HK     = (const int*)  d_in[3];
    const float* kappa_K    = (const float*)d_in[4];
    const float* kappa_H    = (const float*)d_in[5];
    const float* weights_H  = (const float*)d_in[6];
    const float* bias_H     = (const float*)d_in[7];
    const float* weights_HK = (const float*)d_in[8];
    const float* w_K        = (const float*)d_in[9];

    float* fH = (float*)d_out;            // [8192]
    float* fK = fH + N_NODES;             // [8192 * 64]

    prep_kernel<<<1024, 256>>>(state_H, state_K, bias_H, fH);
    fillmv_kernel<<<MV_BLOCKS + FILL_BLOCKS, 256>>>(
        weights_H, ind_K, w_K, ind_HK, weights_HK, fH);
    gather_kernel<<<NODE_BLOCKS, 256>>>(kappa_K, kappa_H, fH, fK);
}

// round 6
// speedup vs baseline: 1.4720x; 1.0211x over previous
#include <cuda_runtime.h>
#include <cstddef>

#define N_NODES 8192
#define D_OSC   64
#define E_EDGES 1048576
#define CAP     512          // slots per node per list (mean 256, sd 16)

#define R_TILE    64
#define MV_BLOCKS 256
#define GATHER_BLOCKS (N_NODES / 4)         // 4 nodes/block, 2 warps (K,HK)/node
#define FILL_BLOCKS ((2 * E_EDGES) / 256)   // 8192

#define QSCALE     32767.0f
#define QSCALE_INV (1.0f / 32767.0f)

// Scratch (device globals — no allocation allowed)
__device__ float d_P[N_NODES * D_OSC];      // normalized state_K (fp32)
__device__ short d_Pq[N_NODES * D_OSC];     // int16-quantized P (gathers), 1MB
__device__ float d_g[N_NODES];              // tanh(state_H)
__device__ int   d_cntK[N_NODES];
__device__ int   d_cntHK[N_NODES];
__device__ int2  d_slotK[N_NODES * CAP];    // (other, w)
__device__ int2  d_slotHK[N_NODES * CAP];   // (other, w * g[other])

// -------------------------------------------------------------------------
// prep: normalize state_K rows -> d_P + d_Pq, g = tanh(state_H),
//       fH = bias - state_H, zero slot counters.
// -------------------------------------------------------------------------
__global__ void prep_kernel(const float* __restrict__ state_H,
                            const float* __restrict__ state_K,
                            const float* __restrict__ bias_H,
                            float* __restrict__ fH) {
    int tid  = blockIdx.x * blockDim.x + threadIdx.x;
    int warp = tid >> 5;
    int lane = threadIdx.x & 31;

    if (warp < N_NODES) {
        const float2* src = reinterpret_cast<const float2*>(state_K + warp * D_OSC);
        float2 u = src[lane];
        float ss = u.x * u.x + u.y * u.y;
        #pragma unroll
        for (int o = 16; o; o >>= 1) ss += __shfl_xor_sync(0xffffffffu, ss, o);
        float inv = rsqrtf(ss);
        float2 val = make_float2(u.x * inv, u.y * inv);
        reinterpret_cast<float2*>(d_P + warp * D_OSC)[lane] = val;
        short2 q;
        q.x = (short)__float2int_rn(val.x * QSCALE);
        q.y = (short)__float2int_rn(val.y * QSCALE);
        reinterpret_cast<short2*>(d_Pq + warp * D_OSC)[lane] = q;
    }
    if (tid < N_NODES) {
        float h = state_H[tid];
        d_g[tid] = tanhf(h);
        fH[tid]  = bias_H[tid] - h;
        d_cntK[tid]  = 0;
        d_cntHK[tid] = 0;
    }
}

// -------------------------------------------------------------------------
// fill: build per-node endpoint lists. HK slots fold g[other] into w.
// -------------------------------------------------------------------------
__global__ void fill_kernel(const int*   __restrict__ indK,
                            const float* __restrict__ wK,
                            const int*   __restrict__ indHK,
                            const float* __restrict__ wHK) {
    int e = blockIdx.x * blockDim.x + threadIdx.x;
    if (e < E_EDGES) {
        int i0 = __ldg(indK + 2 * e);
        int i1 = __ldg(indK + 2 * e + 1);
        int wi = __float_as_int(__ldg(wK + e));
        int p0 = atomicAdd(d_cntK + i0, 1);
        if (p0 < CAP) d_slotK[i0 * CAP + p0] = make_int2(i1, wi);
        int p1 = atomicAdd(d_cntK + i1, 1);
        if (p1 < CAP) d_slotK[i1 * CAP + p1] = make_int2(i0, wi);
    } else {
        e -= E_EDGES;
        int i0 = __ldg(indHK + 2 * e);
        int i1 = __ldg(indHK + 2 * e + 1);
        float w = __ldg(wHK + e);
        float wg1 = w * __ldg(d_g + i1);   // stored with endpoint i0
        float wg0 = w * __ldg(d_g + i0);   // stored with endpoint i1
        int p0 = atomicAdd(d_cntHK + i0, 1);
        if (p0 < CAP) d_slotHK[i0 * CAP + p0] = make_int2(i1, __float_as_int(wg1));
        int p1 = atomicAdd(d_cntHK + i1, 1);
        if (p1 < CAP) d_slotHK[i1 * CAP + p1] = make_int2(i0, __float_as_int(wg0));
    }
}

// -------------------------------------------------------------------------
// Fused matvec tile: one pass over W computes both W@g (y) and W^T@g (z).
// -------------------------------------------------------------------------
__device__ __forceinline__ void mv_work(const float* __restrict__ W,
                                        float* __restrict__ fH, int bid) {
    int strip = bid >> 1;
    int chalf = bid & 1;
    int warp  = threadIdx.x >> 5;
    int lane  = threadIdx.x & 31;

    int r0    = strip * R_TILE;
    int cbase = chalf * 4096 + warp * 512;

    float4 gv[4];
    float4 za[4];
    #pragma unroll
    for (int k = 0; k < 4; k++) {
        gv[k] = *reinterpret_cast<const float4*>(d_g + cbase + k * 128 + lane * 4);
        za[k] = make_float4(0.f, 0.f, 0.f, 0.f);
    }

    for (int r = 0; r < R_TILE; r++) {
        float gr = d_g[r0 + r];
        const float4* Wrow = reinterpret_cast<const float4*>(
            W + (size_t)(r0 + r) * N_NODES + cbase);
        float yp = 0.0f;
        #pragma unroll
        for (int k = 0; k < 4; k++) {
            float4 w4 = __ldg(Wrow + k * 32 + lane);
            yp += w4.x * gv[k].x + w4.y * gv[k].y + w4.z * gv[k].z + w4.w * gv[k].w;
            za[k].x += w4.x * gr;
            za[k].y += w4.y * gr;
            za[k].z += w4.z * gr;
            za[k].w += w4.w * gr;
        }
        #pragma unroll
        for (int o = 16; o; o >>= 1) yp += __shfl_xor_sync(0xffffffffu, yp, o);
        if (lane == 0) atomicAdd(fH + r0 + r, 0.5f * yp);
    }
    #pragma unroll
    for (int k = 0; k < 4; k++) {
        int c = cbase + k * 128 + lane * 4;
        atomicAdd(fH + c + 0, 0.5f * za[k].x);
        atomicAdd(fH + c + 1, 0.5f * za[k].y);
        atomicAdd(fH + c + 2, 0.5f * za[k].z);
        atomicAdd(fH + c + 3, 0.5f * za[k].w);
    }
}

// -------------------------------------------------------------------------
// Pipelined list walk: warp per (node, list); half-warp h processes
// endpoints k+h. Depth-1 software pipeline hides slot->v address dependency.
// -------------------------------------------------------------------------
template<bool HK>
__device__ __forceinline__ void walk_list(const int2* __restrict__ slots,
                                          int cnt, float4 p, float gn,
                                          int half, int hl,
                                          float& ax, float& ay,
                                          float& az, float& aw,
                                          float& fhraw) {
    int idx = half;
    bool ok = idx < cnt;
    int2 ent = __ldg(slots + (ok ? idx : 0));
    int row = ok ? ent.x : 0;
    int2 q = __ldg(reinterpret_cast<const int2*>(d_Pq + row * D_OSC) + hl);

    for (int k = 0; k < cnt; k += 2) {
        // prefetch next iteration
        int nidx = k + 2 + half;
        bool nok = nidx < cnt;
        int2 nent = __ldg(slots + (nok ? nidx : 0));
        int nrow = nok ? nent.x : 0;
        int2 nq = __ldg(reinterpret_cast<const int2*>(d_Pq + nrow * D_OSC) + hl);

        // compute current
        float u0 = (float)(short)(q.x);
        float u1 = (float)(q.x >> 16);
        float u2 = (float)(short)(q.y);
        float u3 = (float)(q.y >> 16);
        float s = p.x * u0 + p.y * u1 + p.z * u2 + p.w * u3;
        #pragma unroll
        for (int o = 8; o; o >>= 1) s += __shfl_xor_sync(0xffffffffu, s, o);

        float w = ok ? __int_as_float(ent.y) : 0.0f;
        float c;
        if (HK) {
            fhraw += s * w;        // w is (w_hk * g_other)
            c = -gn * w;
        } else {
            c = w * s;
        }
        ax += c * u0; ay += c * u1; az += c * u2; aw += c * u3;

        ent = nent; q = nq; ok = nok;
    }
}

// -------------------------------------------------------------------------
// Mega-kernel:
//   blocks [0, MV_BLOCKS)   : fused matvec (DRAM-bound)
//   blocks [MV_BLOCKS, ...) : gather — 4 nodes/block, warp pair (K, HK)
//                             per node, smem combine, projection, write fK.
// -------------------------------------------------------------------------
__global__ void __launch_bounds__(256)
mega_kernel(const float* __restrict__ W,
            const float* __restrict__ kappa_K,
            const float* __restrict__ kappa_H,
            float* __restrict__ fH,
            float* __restrict__ fK) {
    __shared__ float sAcc[4][D_OSC];
    int bid = blockIdx.x;
    if (bid < MV_BLOCKS) {
        mv_work(W, fH, bid);
        return;
    }

    int warp = threadIdx.x >> 5;
    int lane = threadIdx.x & 31;
    int slot4 = warp >> 1;                      // node slot within block 0..3
    int isHK  = warp & 1;
    int node  = (bid - MV_BLOCKS) * 4 + slot4;
    int half  = lane >> 4;
    int hl    = lane & 15;

    float4 p = *reinterpret_cast<const float4*>(d_P + node * D_OSC + hl * 4);
    float gn = __ldg(d_g + node);

    int cnt = isHK ? __ldg(d_cntHK + node) : __ldg(d_cntK + node);
    if (cnt > CAP) cnt = CAP;
    const int2* slots = (isHK ? d_slotHK : d_slotK) + node * CAP;

    float ax = 0.f, ay = 0.f, az = 0.f, aw = 0.f, fhraw = 0.f;
    if (isHK) walk_list<true >(slots, cnt, p, gn, half, hl, ax, ay, az, aw, fhraw);
    else      walk_list<false>(slots, cnt, p, gn, half, hl, ax, ay, az, aw, fhraw);

    // combine the two half-warps (each processed alternating endpoints)
    ax += __shfl_xor_sync(0xffffffffu, ax, 16);
    ay += __shfl_xor_sync(0xffffffffu, ay, 16);
    az += __shfl_xor_sync(0xffffffffu, az, 16);
    aw += __shfl_xor_sync(0xffffffffu, aw, 16);

    float invKK = 1.0f / __ldg(kappa_K);
    float invKH = 1.0f / __ldg(kappa_H);

    if (isHK) {
        // fH: fhraw identical within each half after reduce; sum halves
        float fh = fhraw + __shfl_xor_sync(0xffffffffu, fhraw, 16);
        if (lane == 0) atomicAdd(fH + node, fh * QSCALE_INV * invKH);
        // publish HK acc (scaled) to smem for the K warp
        float sc = QSCALE_INV * invKK;
        if (half == 0) {
            float* dst = sAcc[slot4] + hl * 4;
            dst[0] = ax * sc; dst[1] = ay * sc; dst[2] = az * sc; dst[3] = aw * sc;
        }
    }
    __syncthreads();
    if (!isHK) {
        float sc = QSCALE_INV * QSCALE_INV;
        const float* src = sAcc[slot4] + hl * 4;
        ax = ax * sc + src[0];
        ay = ay * sc + src[1];
        az = az * sc + src[2];
        aw = aw * sc + src[3];

        // projection f_K = -a + P * <P, a>
        float dot = p.x * ax + p.y * ay + p.z * az + p.w * aw;
        #pragma unroll
        for (int o = 8; o; o >>= 1) dot += __shfl_xor_sync(0xffffffffu, dot, o);

        if (half == 0) {
            float4 out = make_float4(-ax + p.x * dot, -ay + p.y * dot,
                                     -az + p.z * dot, -aw + p.w * dot);
            *reinterpret_cast<float4*>(fK + node * D_OSC + hl * 4) = out;
        }
    }
}

// -------------------------------------------------------------------------
extern "C" void kernel_launch(void* const* d_in, const int* in_sizes, int n_in,
                              void* d_out, int out_size) {
    const float* state_H    = (const float*)d_in[0];
    const float* state_K    = (const float*)d_in[1];
    const int*   ind_K      = (const int*)  d_in[2];
    const int*   ind_HK     = (const int*)  d_in[3];
    const float* kappa_K    = (const float*)d_in[4];
    const float* kappa_H    = (const float*)d_in[5];
    const float* weights_H  = (const float*)d_in[6];
    const float* bias_H     = (const float*)d_in[7];
    const float* weights_HK = (const float*)d_in[8];
    const float* w_K        = (const float*)d_in[9];

    float* fH = (float*)d_out;            // [8192]
    float* fK = fH + N_NODES;             // [8192 * 64]

    prep_kernel<<<1024, 256>>>(state_H, state_K, bias_H, fH);
    fill_kernel<<<FILL_BLOCKS, 256>>>(ind_K, w_K, ind_HK, weights_HK);
    mega_kernel<<<MV_BLOCKS + GATHER_BLOCKS, 256>>>(
        weights_H, kappa_K, kappa_H, fH, fK);
}

// round 7
// speedup vs baseline: 1.6558x; 1.1248x over previous
#include <cuda_runtime.h>
#include <cstddef>

#define N_NODES 8192
#define D_OSC   64
#define E_EDGES 1048576
#define CAP     512          // slots per node per list (mean 256, sd 16)

#define R_TILE    64
#define MV_BLOCKS 256
#define FILL_BLOCKS ((2 * E_EDGES) / 256)   // 8192
#define GATHER_BLOCKS (N_NODES / 4)         // 4 nodes/block, warp pair per node

#define QSCALE     32767.0f
#define QSCALE_INV (1.0f / 32767.0f)

// Scratch (device globals — no allocation allowed)
__device__ float d_P[N_NODES * D_OSC];      // normalized state_K (fp32)
__device__ short d_Pq[N_NODES * D_OSC];     // int16-quantized P (gathers), 1MB
__device__ float d_g[N_NODES];              // tanh(state_H)
__device__ int   d_cntK[N_NODES];
__device__ int   d_cntHK[N_NODES];
__device__ int2  d_slotK[N_NODES * CAP];    // (other, w)
__device__ int2  d_slotHK[N_NODES * CAP];   // (other, w * g[other])

// -------------------------------------------------------------------------
// prep
// -------------------------------------------------------------------------
__global__ void prep_kernel(const float* __restrict__ state_H,
                            const float* __restrict__ state_K,
                            const float* __restrict__ bias_H,
                            float* __restrict__ fH) {
    int tid  = blockIdx.x * blockDim.x + threadIdx.x;
    int warp = tid >> 5;
    int lane = threadIdx.x & 31;

    if (warp < N_NODES) {
        const float2* src = reinterpret_cast<const float2*>(state_K + warp * D_OSC);
        float2 u = src[lane];
        float ss = u.x * u.x + u.y * u.y;
        #pragma unroll
        for (int o = 16; o; o >>= 1) ss += __shfl_xor_sync(0xffffffffu, ss, o);
        float inv = rsqrtf(ss);
        float2 val = make_float2(u.x * inv, u.y * inv);
        reinterpret_cast<float2*>(d_P + warp * D_OSC)[lane] = val;
        short2 q;
        q.x = (short)__float2int_rn(val.x * QSCALE);
        q.y = (short)__float2int_rn(val.y * QSCALE);
        reinterpret_cast<short2*>(d_Pq + warp * D_OSC)[lane] = q;
    }
    if (tid < N_NODES) {
        float h = state_H[tid];
        d_g[tid] = tanhf(h);
        fH[tid]  = bias_H[tid] - h;
        d_cntK[tid]  = 0;
        d_cntHK[tid] = 0;
    }
}

// -------------------------------------------------------------------------
// Fused matvec tile: one pass over W computes both W@g (y) and W^T@g (z).
// -------------------------------------------------------------------------
__device__ __forceinline__ void mv_work(const float* __restrict__ W,
                                        float* __restrict__ fH, int bid) {
    int strip = bid >> 1;
    int chalf = bid & 1;
    int warp  = threadIdx.x >> 5;
    int lane  = threadIdx.x & 31;

    int r0    = strip * R_TILE;
    int cbase = chalf * 4096 + warp * 512;

    float4 gv[4];
    float4 za[4];
    #pragma unroll
    for (int k = 0; k < 4; k++) {
        gv[k] = *reinterpret_cast<const float4*>(d_g + cbase + k * 128 + lane * 4);
        za[k] = make_float4(0.f, 0.f, 0.f, 0.f);
    }

    for (int r = 0; r < R_TILE; r++) {
        float gr = d_g[r0 + r];
        const float4* Wrow = reinterpret_cast<const float4*>(
            W + (size_t)(r0 + r) * N_NODES + cbase);
        float yp = 0.0f;
        #pragma unroll
        for (int k = 0; k < 4; k++) {
            float4 w4 = __ldg(Wrow + k * 32 + lane);
            yp += w4.x * gv[k].x + w4.y * gv[k].y + w4.z * gv[k].z + w4.w * gv[k].w;
            za[k].x += w4.x * gr;
            za[k].y += w4.y * gr;
            za[k].z += w4.z * gr;
            za[k].w += w4.w * gr;
        }
        #pragma unroll
        for (int o = 16; o; o >>= 1) yp += __shfl_xor_sync(0xffffffffu, yp, o);
        if (lane == 0) atomicAdd(fH + r0 + r, 0.5f * yp);
    }
    #pragma unroll
    for (int k = 0; k < 4; k++) {
        int c = cbase + k * 128 + lane * 4;
        atomicAdd(fH + c + 0, 0.5f * za[k].x);
        atomicAdd(fH + c + 1, 0.5f * za[k].y);
        atomicAdd(fH + c + 2, 0.5f * za[k].z);
        atomicAdd(fH + c + 3, 0.5f * za[k].w);
    }
}

// -------------------------------------------------------------------------
// fillmv: MV blocks (DRAM-bound) overlapped with list build (latency-bound).
// HK slots store (other, w * g[other]).
// -------------------------------------------------------------------------
__global__ void __launch_bounds__(256)
fillmv_kernel(const float* __restrict__ W,
              const int*   __restrict__ indK,
              const float* __restrict__ wK,
              const int*   __restrict__ indHK,
              const float* __restrict__ wHK,
              float* __restrict__ fH) {
    int bid = blockIdx.x;
    if (bid < MV_BLOCKS) {
        mv_work(W, fH, bid);
        return;
    }
    int e = (bid - MV_BLOCKS) * 256 + threadIdx.x;
    if (e < E_EDGES) {
        int i0 = __ldg(indK + 2 * e);
        int i1 = __ldg(indK + 2 * e + 1);
        int wi = __float_as_int(__ldg(wK + e));
        int p0 = atomicAdd(d_cntK + i0, 1);
        if (p0 < CAP) d_slotK[i0 * CAP + p0] = make_int2(i1, wi);
        int p1 = atomicAdd(d_cntK + i1, 1);
        if (p1 < CAP) d_slotK[i1 * CAP + p1] = make_int2(i0, wi);
    } else {
        e -= E_EDGES;
        int i0 = __ldg(indHK + 2 * e);
        int i1 = __ldg(indHK + 2 * e + 1);
        float w = __ldg(wHK + e);
        float wg1 = w * __ldg(d_g + i1);
        float wg0 = w * __ldg(d_g + i0);
        int p0 = atomicAdd(d_cntHK + i0, 1);
        if (p0 < CAP) d_slotHK[i0 * CAP + p0] = make_int2(i1, __float_as_int(wg1));
        int p1 = atomicAdd(d_cntHK + i1, 1);
        if (p1 < CAP) d_slotHK[i1 * CAP + p1] = make_int2(i0, __float_as_int(wg0));
    }
}

// -------------------------------------------------------------------------
// Gather: warp per (node, list). 8 lanes per endpoint -> 4 endpoints per
// warp-iteration. Lane owns 8 dims (int4 = 8 int16). One q-LDG fetches 4 rows.
// -------------------------------------------------------------------------
template<bool HK>
__device__ __forceinline__ void walk_list(const int2* __restrict__ slots,
                                          int cnt, const float* __restrict__ pl,
                                          float gn, int grp, int gl,
                                          float* __restrict__ acc,
                                          float& fhraw) {
    int idx = grp;
    bool ok = idx < cnt;
    int2 ent = __ldg(slots + (ok ? idx : 0));
    int4 q = __ldg(reinterpret_cast<const int4*>(d_Pq + ent.x * D_OSC) + gl);

    for (int k = 0; k < cnt; k += 4) {
        // prefetch next iteration (4 endpoints ahead)
        int nidx = k + 4 + grp;
        bool nok = nidx < cnt;
        int2 nent = __ldg(slots + (nok ? nidx : 0));
        int4 nq = __ldg(reinterpret_cast<const int4*>(d_Pq + nent.x * D_OSC) + gl);

        // decode 8 int16 -> fp32 (raw)
        float u[8];
        u[0] = (float)(short)(q.x);  u[1] = (float)(q.x >> 16);
        u[2] = (float)(short)(q.y);  u[3] = (float)(q.y >> 16);
        u[4] = (float)(short)(q.z);  u[5] = (float)(q.z >> 16);
        u[6] = (float)(short)(q.w);  u[7] = (float)(q.w >> 16);

        float s = 0.0f;
        #pragma unroll
        for (int i = 0; i < 8; i++) s += pl[i] * u[i];
        // reduce within 8-lane group
        s += __shfl_xor_sync(0xffffffffu, s, 4);
        s += __shfl_xor_sync(0xffffffffu, s, 2);
        s += __shfl_xor_sync(0xffffffffu, s, 1);

        float w = ok ? __int_as_float(ent.y) : 0.0f;
        float c;
        if (HK) {
            fhraw += s * w;          // w is (w_hk * g_other); same across group
            c = -gn * w;
        } else {
            c = w * s;
        }
        #pragma unroll
        for (int i = 0; i < 8; i++) acc[i] += c * u[i];

        ent = nent; q = nq; ok = nok;
    }
}

__global__ void __launch_bounds__(256)
gather_kernel(const float* __restrict__ kappa_K,
              const float* __restrict__ kappa_H,
              float* __restrict__ fH,
              float* __restrict__ fK) {
    __shared__ float sAcc[4][D_OSC];

    int warp  = threadIdx.x >> 5;
    int lane  = threadIdx.x & 31;
    int slot4 = warp >> 1;                 // node slot in block 0..3
    int isHK  = warp & 1;
    int node  = blockIdx.x * 4 + slot4;
    int grp   = lane >> 3;                 // endpoint group 0..3
    int gl    = lane & 7;                  // lane in group; owns dims gl*8..+7

    // own row (fp32, real scale): 8 dims per lane
    float pl[8];
    {
        float4 a = *reinterpret_cast<const float4*>(d_P + node * D_OSC + gl * 8);
        float4 b = *reinterpret_cast<const float4*>(d_P + node * D_OSC + gl * 8 + 4);
        pl[0]=a.x; pl[1]=a.y; pl[2]=a.z; pl[3]=a.w;
        pl[4]=b.x; pl[5]=b.y; pl[6]=b.z; pl[7]=b.w;
    }
    float gn = __ldg(d_g + node);

    int cnt = isHK ? __ldg(d_cntHK + node) : __ldg(d_cntK + node);
    if (cnt > CAP) cnt = CAP;
    const int2* slots = (isHK ? d_slotHK : d_slotK) + node * CAP;

    float acc[8] = {0,0,0,0,0,0,0,0};
    float fhraw = 0.0f;

    if (isHK) walk_list<true >(slots, cnt, pl, gn, grp, gl, acc, fhraw);
    else      walk_list<false>(slots, cnt, pl, gn, grp, gl, acc, fhraw);

    // combine across the 4 endpoint-groups (same dims per gl)
    #pragma unroll
    for (int i = 0; i < 8; i++) {
        acc[i] += __shfl_xor_sync(0xffffffffu, acc[i], 8);
        acc[i] += __shfl_xor_sync(0xffffffffu, acc[i], 16);
    }

    float invKK = 1.0f / __ldg(kappa_K);
    float invKH = 1.0f / __ldg(kappa_H);

    if (isHK) {
        // fhraw: identical within each group after the s-reduce; sum groups
        float fh = fhraw;
        fh += __shfl_xor_sync(0xffffffffu, fh, 8);
        fh += __shfl_xor_sync(0xffffffffu, fh, 16);
        if (lane == 0) atomicAdd(fH + node, fh * QSCALE_INV * invKH);

        float sc = QSCALE_INV * invKK;       // HK acc carries one raw factor
        if (grp == 0) {
            float* dst = sAcc[slot4] + gl * 8;
            #pragma unroll
            for (int i = 0; i < 8; i++) dst[i] = acc[i] * sc;
        }
    }
    __syncthreads();
    if (!isHK) {
        float sc = QSCALE_INV * QSCALE_INV;  // K acc carries two raw factors
        const float* src = sAcc[slot4] + gl * 8;
        #pragma unroll
        for (int i = 0; i < 8; i++) acc[i] = acc[i] * sc + src[i];

        // projection f_K = -a + P * <P, a>
        float dot = 0.0f;
        #pragma unroll
        for (int i = 0; i < 8; i++) dot += pl[i] * acc[i];
        dot += __shfl_xor_sync(0xffffffffu, dot, 4);
        dot += __shfl_xor_sync(0xffffffffu, dot, 2);
        dot += __shfl_xor_sync(0xffffffffu, dot, 1);

        if (grp == 0) {
            float4 o0 = make_float4(-acc[0] + pl[0] * dot, -acc[1] + pl[1] * dot,
                                    -acc[2] + pl[2] * dot, -acc[3] + pl[3] * dot);
            float4 o1 = make_float4(-acc[4] + pl[4] * dot, -acc[5] + pl[5] * dot,
                                    -acc[6] + pl[6] * dot, -acc[7] + pl[7] * dot);
            *reinterpret_cast<float4*>(fK + node * D_OSC + gl * 8)     = o0;
            *reinterpret_cast<float4*>(fK + node * D_OSC + gl * 8 + 4) = o1;
        }
    }
}

// -------------------------------------------------------------------------
extern "C" void kernel_launch(void* const* d_in, const int* in_sizes, int n_in,
                              void* d_out, int out_size) {
    const float* state_H    = (const float*)d_in[0];
    const float* state_K    = (const float*)d_in[1];
    const int*   ind_K      = (const int*)  d_in[2];
    const int*   ind_HK     = (const int*)  d_in[3];
    const float* kappa_K    = (const float*)d_in[4];
    const float* kappa_H    = (const float*)d_in[5];
    const float* weights_H  = (const float*)d_in[6];
    const float* bias_H     = (const float*)d_in[7];
    const float* weights_HK = (const float*)d_in[8];
    const float* w_K        = (const float*)d_in[9];

    float* fH = (float*)d_out;            // [8192]
    float* fK = fH + N_NODES;             // [8192 * 64]

    prep_kernel<<<1024, 256>>>(state_H, state_K, bias_H, fH);
    fillmv_kernel<<<MV_BLOCKS + FILL_BLOCKS, 256>>>(
        weights_H, ind_K, w_K, ind_HK, weights_HK, fH);
    gather_kernel<<<GATHER_BLOCKS, 256>>>(kappa_K, kappa_H, fH, fK);
}

// round 8
// speedup vs baseline: 1.8268x; 1.1033x over previous
#include <cuda_runtime.h>
#include <cstddef>

#define N_NODES 8192
#define D_OSC   64
#define E_EDGES 1048576
#define CAP     512          // slots per node per list (mean 256, sd 16)

#define R_TILE    64
#define MV_BLOCKS 256
#define PREP_BLOCKS 1024
#define FILL_BLOCKS ((2 * E_EDGES) / 256)   // 8192
#define GATHER_BLOCKS (N_NODES / 4)         // 4 nodes/block, warp pair per node

#define QSCALE     32767.0f
#define QSCALE_INV (1.0f / 32767.0f)

// Scratch (device globals — no allocation allowed)
__device__ float d_P[N_NODES * D_OSC];      // normalized state_K (fp32)
__device__ short d_Pq[N_NODES * D_OSC];     // int16-quantized P (gathers), 1MB
__device__ float d_g[N_NODES];              // tanh(state_H)
__device__ int   d_cntK[N_NODES];
__device__ int   d_cntHK[N_NODES];
__device__ int2  d_slotK[N_NODES * CAP];    // (other, w)
__device__ int2  d_slotHK[N_NODES * CAP];   // (other, w * g[other])

// -------------------------------------------------------------------------
// zero: counters must be 0 before fill's atomics
// -------------------------------------------------------------------------
__global__ void zero_kernel() {
    int tid = blockIdx.x * blockDim.x + threadIdx.x;
    if (tid < N_NODES) {
        d_cntK[tid]  = 0;
        d_cntHK[tid] = 0;
    }
}

// -------------------------------------------------------------------------
// prepfill: blocks [0, PREP_BLOCKS) normalize K rows -> d_P/d_Pq, compute
// d_g, init fH. Remaining blocks build edge lists, computing tanh inline
// (no dependency on the prep blocks).
// -------------------------------------------------------------------------
__global__ void __launch_bounds__(256)
prepfill_kernel(const float* __restrict__ state_H,
                const float* __restrict__ state_K,
                const float* __restrict__ bias_H,
                const int*   __restrict__ indK,
                const float* __restrict__ wK,
                const int*   __restrict__ indHK,
                const float* __restrict__ wHK,
                float* __restrict__ fH) {
    int bid = blockIdx.x;
    if (bid < PREP_BLOCKS) {
        int tid  = bid * blockDim.x + threadIdx.x;
        int warp = tid >> 5;
        int lane = threadIdx.x & 31;

        const float2* src = reinterpret_cast<const float2*>(state_K + warp * D_OSC);
        float2 u = src[lane];
        float ss = u.x * u.x + u.y * u.y;
        #pragma unroll
        for (int o = 16; o; o >>= 1) ss += __shfl_xor_sync(0xffffffffu, ss, o);
        float inv = rsqrtf(ss);
        float2 val = make_float2(u.x * inv, u.y * inv);
        reinterpret_cast<float2*>(d_P + warp * D_OSC)[lane] = val;
        short2 q;
        q.x = (short)__float2int_rn(val.x * QSCALE);
        q.y = (short)__float2int_rn(val.y * QSCALE);
        reinterpret_cast<short2*>(d_Pq + warp * D_OSC)[lane] = q;

        if (tid < N_NODES) {
            float h = state_H[tid];
            d_g[tid] = tanhf(h);
            fH[tid]  = bias_H[tid] - h;
        }
        return;
    }

    int e = (bid - PREP_BLOCKS) * 256 + threadIdx.x;
    if (e < E_EDGES) {
        int i0 = __ldg(indK + 2 * e);
        int i1 = __ldg(indK + 2 * e + 1);
        int wi = __float_as_int(__ldg(wK + e));
        int p0 = atomicAdd(d_cntK + i0, 1);
        if (p0 < CAP) d_slotK[i0 * CAP + p0] = make_int2(i1, wi);
        int p1 = atomicAdd(d_cntK + i1, 1);
        if (p1 < CAP) d_slotK[i1 * CAP + p1] = make_int2(i0, wi);
    } else {
        e -= E_EDGES;
        int i0 = __ldg(indHK + 2 * e);
        int i1 = __ldg(indHK + 2 * e + 1);
        float w = __ldg(wHK + e);
        float g0 = tanhf(__ldg(state_H + i0));   // inline: no prep dependency
        float g1 = tanhf(__ldg(state_H + i1));
        int p0 = atomicAdd(d_cntHK + i0, 1);
        if (p0 < CAP) d_slotHK[i0 * CAP + p0] = make_int2(i1, __float_as_int(w * g1));
        int p1 = atomicAdd(d_cntHK + i1, 1);
        if (p1 < CAP) d_slotHK[i1 * CAP + p1] = make_int2(i0, __float_as_int(w * g0));
    }
}

// -------------------------------------------------------------------------
// Fused matvec tile: one pass over W computes both W@g (y) and W^T@g (z).
// -------------------------------------------------------------------------
__device__ __forceinline__ void mv_work(const float* __restrict__ W,
                                        float* __restrict__ fH, int bid) {
    int strip = bid >> 1;
    int chalf = bid & 1;
    int warp  = threadIdx.x >> 5;
    int lane  = threadIdx.x & 31;

    int r0    = strip * R_TILE;
    int cbase = chalf * 4096 + warp * 512;

    float4 gv[4];
    float4 za[4];
    #pragma unroll
    for (int k = 0; k < 4; k++) {
        gv[k] = *reinterpret_cast<const float4*>(d_g + cbase + k * 128 + lane * 4);
        za[k] = make_float4(0.f, 0.f, 0.f, 0.f);
    }

    for (int r = 0; r < R_TILE; r++) {
        float gr = d_g[r0 + r];
        const float4* Wrow = reinterpret_cast<const float4*>(
            W + (size_t)(r0 + r) * N_NODES + cbase);
        float yp = 0.0f;
        #pragma unroll
        for (int k = 0; k < 4; k++) {
            float4 w4 = __ldg(Wrow + k * 32 + lane);
            yp += w4.x * gv[k].x + w4.y * gv[k].y + w4.z * gv[k].z + w4.w * gv[k].w;
            za[k].x += w4.x * gr;
            za[k].y += w4.y * gr;
            za[k].z += w4.z * gr;
            za[k].w += w4.w * gr;
        }
        #pragma unroll
        for (int o = 16; o; o >>= 1) yp += __shfl_xor_sync(0xffffffffu, yp, o);
        if (lane == 0) atomicAdd(fH + r0 + r, 0.5f * yp);
    }
    #pragma unroll
    for (int k = 0; k < 4; k++) {
        int c = cbase + k * 128 + lane * 4;
        atomicAdd(fH + c + 0, 0.5f * za[k].x);
        atomicAdd(fH + c + 1, 0.5f * za[k].y);
        atomicAdd(fH + c + 2, 0.5f * za[k].z);
        atomicAdd(fH + c + 3, 0.5f * za[k].w);
    }
}

// -------------------------------------------------------------------------
// Pipelined list walk: 8 lanes per endpoint, 4 endpoints per warp-iteration.
// Slots prefetched at depth 3, rows at depth 2 (hides L2 slot->row chain).
// -------------------------------------------------------------------------
template<bool HK>
__device__ __forceinline__ void walk_list(const int2* __restrict__ slots,
                                          int cnt, const float* __restrict__ pl,
                                          float gn, int grp, int gl,
                                          float* __restrict__ acc,
                                          float& fhraw) {
    int iA = grp, iB = 4 + grp, iC = 8 + grp;
    int2 eA = __ldg(slots + (iA < cnt ? iA : 0));
    int2 eB = __ldg(slots + (iB < cnt ? iB : 0));
    int2 eC = __ldg(slots + (iC < cnt ? iC : 0));
    int4 qA = __ldg(reinterpret_cast<const int4*>(d_Pq + eA.x * D_OSC) + gl);
    int4 qB = __ldg(reinterpret_cast<const int4*>(d_Pq + eB.x * D_OSC) + gl);

    for (int k = 0; k < cnt; k += 4) {
        int ni = k + 12 + grp;
        int2 eD = __ldg(slots + (ni < cnt ? ni : 0));
        int4 qC = __ldg(reinterpret_cast<const int4*>(d_Pq + eC.x * D_OSC) + gl);

        // compute iteration k (entry eA, row qA)
        float u[8];
        u[0] = (float)(short)(qA.x);  u[1] = (float)(qA.x >> 16);
        u[2] = (float)(short)(qA.y);  u[3] = (float)(qA.y >> 16);
        u[4] = (float)(short)(qA.z);  u[5] = (float)(qA.z >> 16);
        u[6] = (float)(short)(qA.w);  u[7] = (float)(qA.w >> 16);

        float s = 0.0f;
        #pragma unroll
        for (int i = 0; i < 8; i++) s += pl[i] * u[i];
        s += __shfl_xor_sync(0xffffffffu, s, 4);
        s += __shfl_xor_sync(0xffffffffu, s, 2);
        s += __shfl_xor_sync(0xffffffffu, s, 1);

        float w = (k + grp < cnt) ? __int_as_float(eA.y) : 0.0f;
        float c;
        if (HK) {
            fhraw += s * w;          // w is (w_hk * g_other); same across group
            c = -gn * w;
        } else {
            c = w * s;
        }
        #pragma unroll
        for (int i = 0; i < 8; i++) acc[i] += c * u[i];

        eA = eB; qA = qB;
        eB = eC; qB = qC;
        eC = eD;
    }
}

// -------------------------------------------------------------------------
// Mega-kernel: blocks [0, MV_BLOCKS) fused matvec; rest gather.
// Gather: 4 nodes/block, warp pair (K, HK) per node, smem combine.
// -------------------------------------------------------------------------
__global__ void __launch_bounds__(256)
mega_kernel(const float* __restrict__ W,
            const float* __restrict__ kappa_K,
            const float* __restrict__ kappa_H,
            float* __restrict__ fH,
            float* __restrict__ fK) {
    __shared__ float sAcc[4][D_OSC];
    int bid = blockIdx.x;
    if (bid < MV_BLOCKS) {
        mv_work(W, fH, bid);
        return;
    }

    int warp  = threadIdx.x >> 5;
    int lane  = threadIdx.x & 31;
    int slot4 = warp >> 1;                 // node slot in block 0..3
    int isHK  = warp & 1;
    int node  = (bid - MV_BLOCKS) * 4 + slot4;
    int grp   = lane >> 3;                 // endpoint group 0..3
    int gl    = lane & 7;                  // lane in group; owns dims gl*8..+7

    float pl[8];
    {
        float4 a = *reinterpret_cast<const float4*>(d_P + node * D_OSC + gl * 8);
        float4 b = *reinterpret_cast<const float4*>(d_P + node * D_OSC + gl * 8 + 4);
        pl[0]=a.x; pl[1]=a.y; pl[2]=a.z; pl[3]=a.w;
        pl[4]=b.x; pl[5]=b.y; pl[6]=b.z; pl[7]=b.w;
    }
    float gn = __ldg(d_g + node);

    int cnt = isHK ? __ldg(d_cntHK + node) : __ldg(d_cntK + node);
    if (cnt > CAP) cnt = CAP;
    const int2* slots = (isHK ? d_slotHK : d_slotK) + node * CAP;

    float acc[8] = {0,0,0,0,0,0,0,0};
    float fhraw = 0.0f;

    if (isHK) walk_list<true >(slots, cnt, pl, gn, grp, gl, acc, fhraw);
    else      walk_list<false>(slots, cnt, pl, gn, grp, gl, acc, fhraw);

    // combine across the 4 endpoint-groups (same dims per gl)
    #pragma unroll
    for (int i = 0; i < 8; i++) {
        acc[i] += __shfl_xor_sync(0xffffffffu, acc[i], 8);
        acc[i] += __shfl_xor_sync(0xffffffffu, acc[i], 16);
    }

    float invKK = 1.0f / __ldg(kappa_K);
    float invKH = 1.0f / __ldg(kappa_H);

    if (isHK) {
        float fh = fhraw;
        fh += __shfl_xor_sync(0xffffffffu, fh, 8);
        fh += __shfl_xor_sync(0xffffffffu, fh, 16);
        if (lane == 0) atomicAdd(fH + node, fh * QSCALE_INV * invKH);

        float sc = QSCALE_INV * invKK;       // HK acc carries one raw factor
        if (grp == 0) {
            float* dst = sAcc[slot4] + gl * 8;
            #pragma unroll
            for (int i = 0; i < 8; i++) dst[i] = acc[i] * sc;
        }
    }
    __syncthreads();
    if (!isHK) {
        float sc = QSCALE_INV * QSCALE_INV;  // K acc carries two raw factors
        const float* src = sAcc[slot4] + gl * 8;
        #pragma unroll
        for (int i = 0; i < 8; i++) acc[i] = acc[i] * sc + src[i];

        // projection f_K = -a + P * <P, a>
        float dot = 0.0f;
        #pragma unroll
        for (int i = 0; i < 8; i++) dot += pl[i] * acc[i];
        dot += __shfl_xor_sync(0xffffffffu, dot, 4);
        dot += __shfl_xor_sync(0xffffffffu, dot, 2);
        dot += __shfl_xor_sync(0xffffffffu, dot, 1);

        if (grp == 0) {
            float4 o0 = make_float4(-acc[0] + pl[0] * dot, -acc[1] + pl[1] * dot,
                                    -acc[2] + pl[2] * dot, -acc[3] + pl[3] * dot);
            float4 o1 = make_float4(-acc[4] + pl[4] * dot, -acc[5] + pl[5] * dot,
                                    -acc[6] + pl[6] * dot, -acc[7] + pl[7] * dot);
            *reinterpret_cast<float4*>(fK + node * D_OSC + gl * 8)     = o0;
            *reinterpret_cast<float4*>(fK + node * D_OSC + gl * 8 + 4) = o1;
        }
    }
}

// -------------------------------------------------------------------------
extern "C" void kernel_launch(void* const* d_in, const int* in_sizes, int n_in,
                              void* d_out, int out_size) {
    const float* state_H    = (const float*)d_in[0];
    const float* state_K    = (const float*)d_in[1];
    const int*   ind_K      = (const int*)  d_in[2];
    const int*   ind_HK     = (const int*)  d_in[3];
    const float* kappa_K    = (const float*)d_in[4];
    const float* kappa_H    = (const float*)d_in[5];
    const float* weights_H  = (const float*)d_in[6];
    const float* bias_H     = (const float*)d_in[7];
    const float* weights_HK = (const float*)d_in[8];
    const float* w_K        = (const float*)d_in[9];

    float* fH = (float*)d_out;            // [8192]
    float* fK = fH + N_NODES;             // [8192 * 64]

    zero_kernel<<<N_NODES / 256, 256>>>();
    prepfill_kernel<<<PREP_BLOCKS + FILL_BLOCKS, 256>>>(
        state_H, state_K, bias_H, ind_K, w_K, ind_HK, weights_HK, fH);
    mega_kernel<<<MV_BLOCKS + GATHER_BLOCKS, 256>>>(
        weights_H, kappa_K, kappa_H, fH, fK);
}